// round 15
// baseline (speedup 1.0000x reference)
#include <cuda_runtime.h>
#include <cuda_fp16.h>
#include <math.h>
#include <stdint.h>

// ---------------- problem constants ----------------
#define NENT   200000
#define NREL   500
#define NNODES 100000
#define NNEW   50000
#define MEDGE  200000
#define EDIM   128
#define HDIM   256
#define QDIM   256
#define BDIM   256
#define SCAN_BLK 256
#define NBLK ((NNEW + SCAN_BLK - 1) / SCAN_BLK)   // 196

// ---------------- device scratch (no allocations allowed) ----------------
__device__ __align__(16) float  g_relWr [NREL * HDIM];
__device__ __align__(16) float  g_relWqr[NREL * HDIM];
__device__ __align__(16) __half g_relC2h[NREL * HDIM];
__device__ __align__(16) float  g_qdot  [BDIM];
__device__ __align__(16) __half g_NHW   [(size_t)NNODES * HDIM];
__device__ __align__(16) __half g_EW1   [(size_t)NENT   * HDIM];
__device__ __align__(16) __half g_agg   [(size_t)NNEW * 2 * EDIM];
__device__ __align__(16) __half g_hprev [(size_t)NNEW * HDIM];
__device__ __align__(16) __half g_GX    [(size_t)NNEW * 3 * HDIM];
__device__ __align__(16) __half g_GH    [(size_t)NNEW * 3 * HDIM];
__device__ __align__(16) __half g_hnew  [(size_t)NNEW * HDIM];
__device__ __align__(16) __half g_HN3   [(size_t)NNEW * HDIM];
// fp16 copies of source embeddings
__device__ __align__(16) __half g_entH  [(size_t)NENT * EDIM];
__device__ __align__(16) __half g_relH  [NREL * EDIM];
// transposed weights [N, K]
__device__ __align__(16) float  g_WsT   [HDIM * HDIM];
__device__ __align__(16) float  g_We2hT [HDIM * EDIM];
__device__ __align__(16) float  g_c1T   [HDIM * EDIM];
__device__ __align__(16) float  g_c3T   [HDIM * HDIM];
// CSR for tail_node aggregation
__device__ int   g_cnt   [NNEW];
__device__ int   g_rowptr[NNEW + 1];
__device__ int   g_colidx[MEDGE];
__device__ float g_alpha [MEDGE];
__device__ int   g_bsum  [NBLK];
__device__ int   g_boff  [NBLK];

// ---------------- helpers ----------------
__device__ __forceinline__ uint32_t smem_u32(const void* p) {
    uint32_t a;
    asm("{ .reg .u64 t; cvta.to.shared.u64 t, %1; cvt.u32.u64 %0, t; }" : "=r"(a) : "l"(p));
    return a;
}

__device__ __forceinline__ void ldmx4(uint32_t addr, uint32_t& r0, uint32_t& r1,
                                      uint32_t& r2, uint32_t& r3) {
    asm volatile("ldmatrix.sync.aligned.m8n8.x4.shared.b16 {%0,%1,%2,%3}, [%4];"
                 : "=r"(r0), "=r"(r1), "=r"(r2), "=r"(r3) : "r"(addr));
}

__device__ __forceinline__ void mma16816(float* c, const uint32_t* a,
                                         uint32_t b0, uint32_t b1) {
    asm volatile(
        "mma.sync.aligned.m16n8k16.row.col.f32.f16.f16.f32 "
        "{%0,%1,%2,%3}, {%4,%5,%6,%7}, {%8,%9}, {%0,%1,%2,%3};"
        : "+f"(c[0]), "+f"(c[1]), "+f"(c[2]), "+f"(c[3])
        : "r"(a[0]), "r"(a[1]), "r"(a[2]), "r"(a[3]), "r"(b0), "r"(b1));
}

__device__ __forceinline__ uint2 pack_h(float4 v) {
    __half2 h01; h01.x = __float2half_rn(v.x); h01.y = __float2half_rn(v.y);
    __half2 h23; h23.x = __float2half_rn(v.z); h23.y = __float2half_rn(v.w);
    return make_uint2(*(uint32_t*)&h01, *(uint32_t*)&h23);
}

__device__ __forceinline__ float4 unpack_h(uint2 u) {
    __half2 h01 = *(__half2*)&u.x;
    __half2 h23 = *(__half2*)&u.y;
    float2 a = __half22float2(h01), b = __half22float2(h23);
    return make_float4(a.x, a.y, b.x, b.y);
}

// ---------------- pipelined HMMA fp16 GEMM ----------------
#define ASTRIDE 40
#define TILE_B  (128 * ASTRIDE * 2)
#define STAGE_B (2 * TILE_B)
#define GEMM_DSMEM (2 * STAGE_B)

template <int EPI, bool GATHER, bool OUTH, bool INH>
__global__ __launch_bounds__(256, 2)
void hmma_gemm(const void* __restrict__ Av, const float* __restrict__ Bt,
               const float* __restrict__ bias, void* __restrict__ Cv,
               int M, int N, int K, const int* __restrict__ gidx)
{
    extern __shared__ char dsm[];
    const uint32_t sb = smem_u32(dsm);

    const int tid = threadIdx.x;
    const int wid = tid >> 5, lane = tid & 31;
    const int bx = blockIdx.x, by = blockIdx.y;
    const int wm = (wid & 3) * 32;
    const int wn = (wid >> 2) * 64;

    float acc[2][8][4];
#pragma unroll
    for (int i = 0; i < 2; i++)
#pragma unroll
        for (int j = 0; j < 8; j++)
#pragma unroll
            for (int u = 0; u < 4; u++) acc[i][j][u] = 0.f;

    const float*  aF[4]; const __half* aHp[4];
    bool av[4]; int soff[4];
    const float* bptr[4];
#pragma unroll
    for (int i = 0; i < 4; i++) {
        int idx = tid + 256 * i;
        int row = idx >> 3, c4 = (idx & 7) * 4;
        int grow = by * 128 + row;
        av[i] = (grow < M);
        size_t phys = 0;
        if (av[i]) phys = GATHER ? (size_t)gidx[grow] : (size_t)grow;
        if (INH) aHp[i] = (const __half*)Av + phys * (size_t)K + c4;
        else     aF[i]  = (const float*)Av + phys * (size_t)K + c4;
        bptr[i] = Bt + (size_t)(bx * 128 + row) * K + c4;
        soff[i] = (row * ASTRIDE + c4) * 2;
    }

    const int lrow = lane & 15;
    const int lk   = (lane >> 4) << 3;
    const uint32_t aoffH = (uint32_t)((wm + lrow) * ASTRIDE + lk) * 2;
    const int brow = (lane & 7) + ((lane >> 4) << 3);
    const int bk   = ((lane >> 3) & 1) << 3;
    const uint32_t boffH = (uint32_t)((wn + brow) * ASTRIDE + bk) * 2;

    const int KT = K >> 5;

    float4 ra[4]; uint2 rah[4]; float4 rb[4];
#pragma unroll
    for (int i = 0; i < 4; i++) {
        if (INH) rah[i] = av[i] ? *(const uint2*)(aHp[i]) : make_uint2(0u, 0u);
        else     ra[i]  = av[i] ? *(const float4*)(aF[i]) : make_float4(0.f, 0.f, 0.f, 0.f);
        rb[i] = *(const float4*)(bptr[i]);
    }

    for (int t = 0; t < KT; t++) {
        const uint32_t stg = (uint32_t)(t & 1) * STAGE_B;
        char* base = dsm + stg;
#pragma unroll
        for (int i = 0; i < 4; i++) {
            *(uint2*)(base + soff[i])          = INH ? rah[i] : pack_h(ra[i]);
            *(uint2*)(base + TILE_B + soff[i]) = pack_h(rb[i]);
        }
        __syncthreads();

        if (t + 1 < KT) {
            const int koff = (t + 1) * 32;
#pragma unroll
            for (int i = 0; i < 4; i++) {
                if (INH) rah[i] = av[i] ? *(const uint2*)(aHp[i] + koff) : make_uint2(0u, 0u);
                else     ra[i]  = av[i] ? *(const float4*)(aF[i] + koff)
                                        : make_float4(0.f, 0.f, 0.f, 0.f);
                rb[i] = *(const float4*)(bptr[i] + koff);
            }
        }

        const uint32_t aH = sb + stg + aoffH;
        const uint32_t bH = sb + stg + TILE_B + boffH;

#pragma unroll
        for (int ks = 0; ks < 32; ks += 16) {
            uint32_t ah[2][4];
#pragma unroll
            for (int mi = 0; mi < 2; mi++) {
                uint32_t off = (uint32_t)(mi * 16 * ASTRIDE + ks) * 2;
                ldmx4(aH + off, ah[mi][0], ah[mi][1], ah[mi][2], ah[mi][3]);
            }
#pragma unroll
            for (int nj = 0; nj < 4; nj++) {
                uint32_t off = (uint32_t)(nj * 16 * ASTRIDE + ks) * 2;
                uint32_t bh[4];
                ldmx4(bH + off, bh[0], bh[1], bh[2], bh[3]);
#pragma unroll
                for (int mi = 0; mi < 2; mi++) {
#pragma unroll
                    for (int h = 0; h < 2; h++)
                        mma16816(acc[mi][nj * 2 + h], ah[mi], bh[h * 2], bh[h * 2 + 1]);
                }
            }
        }
    }

    const int g = lane >> 2, tig = lane & 3;
#pragma unroll
    for (int mi = 0; mi < 2; mi++) {
        const int r0 = by * 128 + wm + mi * 16 + g;
        const int r1 = r0 + 8;
#pragma unroll
        for (int nj = 0; nj < 8; nj++) {
            const int col = bx * 128 + wn + nj * 8 + 2 * tig;
            float b0 = 0.f, b1 = 0.f;
            if (EPI >= 1) { b0 = bias[col]; b1 = bias[col + 1]; }
            float* c = acc[mi][nj];
            float x0 = c[0], x1 = c[1], x2 = c[2], x3 = c[3];
            if (EPI >= 1) { x0 += b0; x1 += b1; x2 += b0; x3 += b1; }
            if (EPI == 2) {
                x0 = (x0 > 0.f) ? x0 : 0.01f * x0;
                x1 = (x1 > 0.f) ? x1 : 0.01f * x1;
                x2 = (x2 > 0.f) ? x2 : 0.01f * x2;
                x3 = (x3 > 0.f) ? x3 : 0.01f * x3;
            }
            if (OUTH) {
                __half* Ch = (__half*)Cv;
                if (r0 < M) {
                    __half2 p; p.x = __float2half_rn(x0); p.y = __float2half_rn(x1);
                    *(uint32_t*)&Ch[(size_t)r0 * N + col] = *(uint32_t*)&p;
                }
                if (r1 < M) {
                    __half2 p; p.x = __float2half_rn(x2); p.y = __float2half_rn(x3);
                    *(uint32_t*)&Ch[(size_t)r1 * N + col] = *(uint32_t*)&p;
                }
            } else {
                float* Cf = (float*)Cv;
                if (r0 < M) *(float2*)&Cf[(size_t)r0 * N + col] = make_float2(x0, x1);
                if (r1 < M) *(float2*)&Cf[(size_t)r1 * N + col] = make_float2(x2, x3);
            }
        }
    }
}

// ---------------- fused weight transposes ----------------
struct TransJob { const float* in; float* out; int K; int N; };

__global__ void transpose4_kernel(TransJob j0, TransJob j1, TransJob j2, TransJob j3)
{
    TransJob jb = (blockIdx.z == 0) ? j0 : (blockIdx.z == 1) ? j1
                 : (blockIdx.z == 2) ? j2 : j3;
    const int k0 = blockIdx.y * 32;
    if (k0 >= jb.K) return;
    __shared__ float t[32][33];
    const int tx = threadIdx.x & 31, ty = threadIdx.x >> 5;
    const int n0 = blockIdx.x * 32;
#pragma unroll
    for (int i = 0; i < 32; i += 8)
        t[ty + i][tx] = jb.in[(size_t)(k0 + ty + i) * jb.N + n0 + tx];
    __syncthreads();
#pragma unroll
    for (int i = 0; i < 32; i += 8)
        jb.out[(size_t)(n0 + ty + i) * jb.K + k0 + tx] = t[tx][ty + i];
}

// ---------------- fp16 conversions of source embeddings ----------------
__global__ void ent_convert_kernel(const float* __restrict__ e)
{
    size_t i = (size_t)blockIdx.x * blockDim.x + threadIdx.x;
    if (i < (size_t)NENT * EDIM / 4)
        ((uint2*)g_entH)[i] = pack_h(((const float4*)e)[i]);
}

__global__ void rel_convert_kernel(const float* __restrict__ r)
{
    size_t i = (size_t)blockIdx.x * blockDim.x + threadIdx.x;
    if (i < (size_t)NREL * EDIM / 4)
        ((uint2*)g_relH)[i] = pack_h(((const float4*)r)[i]);
}

// ---------------- small precompute kernels ----------------
__global__ void rel_precompute(const float* __restrict__ rel_emb,
                               const float* __restrict__ Wr,
                               const float* __restrict__ Wqr,
                               const float* __restrict__ candW,
                               const float* __restrict__ cand_b)
{
    const int r = blockIdx.x;
    const int j = threadIdx.x;
    __shared__ float re[EDIM];
    if (j < EDIM) re[j] = rel_emb[r * EDIM + j];
    __syncthreads();
    float s1 = 0.f, s2 = 0.f, s3 = 0.f;
#pragma unroll 4
    for (int k = 0; k < EDIM; k++) {
        const float rv = re[k];
        s1 = fmaf(rv, Wr[k * HDIM + j], s1);
        s2 = fmaf(rv, Wqr[k * HDIM + j], s2);
        s3 = fmaf(rv, candW[(EDIM + k) * HDIM + j], s3);
    }
    g_relWr[r * HDIM + j]  = s1;
    g_relWqr[r * HDIM + j] = s2;
    g_relC2h[r * HDIM + j] = __float2half_rn(s3 + cand_b[j]);
}

__global__ void qdot_kernel(const float* __restrict__ qrep,
                            const float* __restrict__ rankW)
{
    const int b = blockIdx.x * 8 + (threadIdx.x >> 5);
    const int lane = threadIdx.x & 31;
    if (b >= BDIM) return;
    float s = 0.f;
#pragma unroll
    for (int i = 0; i < 8; i++) {
        int q = lane + 32 * i;
        s = fmaf(qrep[b * QDIM + q], rankW[HDIM + q], s);
    }
#pragma unroll
    for (int o = 16; o > 0; o >>= 1) s += __shfl_xor_sync(0xffffffffu, s, o);
    if (lane == 0) g_qdot[b] = s;
}

// ---------------- CSR build ----------------
__global__ void csr_zero_kernel()
{
    int i = blockIdx.x * blockDim.x + threadIdx.x;
    if (i < NNEW) g_cnt[i] = 0;
}

__global__ void csr_hist_kernel(const int* __restrict__ tnode)
{
    int m = blockIdx.x * blockDim.x + threadIdx.x;
    if (m < MEDGE) atomicAdd(&g_cnt[tnode[m]], 1);
}

// phase 1: per-block exclusive scan + block sums
__global__ __launch_bounds__(SCAN_BLK)
void csr_scan1_kernel()
{
    __shared__ int sh[SCAN_BLK];
    const int i = blockIdx.x * SCAN_BLK + threadIdx.x;
    const int v = (i < NNEW) ? g_cnt[i] : 0;
    sh[threadIdx.x] = v;
    __syncthreads();
#pragma unroll
    for (int off = 1; off < SCAN_BLK; off <<= 1) {
        int t = (threadIdx.x >= off) ? sh[threadIdx.x - off] : 0;
        __syncthreads();
        sh[threadIdx.x] += t;
        __syncthreads();
    }
    if (i < NNEW) g_rowptr[i] = sh[threadIdx.x] - v;       // exclusive, local
    if (threadIdx.x == SCAN_BLK - 1) g_bsum[blockIdx.x] = sh[threadIdx.x];
}

// phase 2: scan the 196 block sums (one block)
__global__ __launch_bounds__(SCAN_BLK)
void csr_scan2_kernel()
{
    __shared__ int sh[SCAN_BLK];
    const int v = (threadIdx.x < NBLK) ? g_bsum[threadIdx.x] : 0;
    sh[threadIdx.x] = v;
    __syncthreads();
#pragma unroll
    for (int off = 1; off < SCAN_BLK; off <<= 1) {
        int t = (threadIdx.x >= off) ? sh[threadIdx.x - off] : 0;
        __syncthreads();
        sh[threadIdx.x] += t;
        __syncthreads();
    }
    if (threadIdx.x < NBLK) g_boff[threadIdx.x] = sh[threadIdx.x] - v;
}

// phase 3: add block offsets, reset cursors, cap rowptr
__global__ void csr_scan3_kernel()
{
    int i = blockIdx.x * blockDim.x + threadIdx.x;
    if (i < NNEW) {
        g_rowptr[i] += g_boff[i / SCAN_BLK];
        g_cnt[i] = 0;
    }
    if (i == 0) g_rowptr[NNEW] = MEDGE;
}

__global__ void csr_fill_kernel(const int* __restrict__ tnode)
{
    int m = blockIdx.x * blockDim.x + threadIdx.x;
    if (m >= MEDGE) return;
    int t = tnode[m];
    int pos = atomicAdd(&g_cnt[t], 1);
    g_colidx[g_rowptr[t] + pos] = m;
}

// ---------------- attention alpha: 8 edges per warp ----------------
__global__ __launch_bounds__(256)
void alpha_kernel(const float* __restrict__ bqr,
                  const float* __restrict__ w_alpha,
                  const float* __restrict__ b_alpha,
                  const int* __restrict__ head,
                  const int* __restrict__ erel,
                  const int* __restrict__ qrel)
{
    const int m0 = (blockIdx.x * 8 + (threadIdx.x >> 5)) * 8;
    if (m0 >= MEDGE) return;
    const int lane = threadIdx.x & 31;

    int hh[8], rr[8], qq[8];
#pragma unroll
    for (int e = 0; e < 8; e++) {
        hh[e] = head[m0 + e]; rr[e] = erel[m0 + e]; qq[e] = qrel[m0 + e];
    }
    uint4 nv[8];
#pragma unroll
    for (int e = 0; e < 8; e++)
        nv[e] = ((const uint4*)(g_NHW + (size_t)hh[e] * HDIM))[lane];

    const float4 bq0 = ((const float4*)bqr)[lane * 2];
    const float4 bq1 = ((const float4*)bqr)[lane * 2 + 1];
    const float4 wa0 = ((const float4*)w_alpha)[lane * 2];
    const float4 wa1 = ((const float4*)w_alpha)[lane * 2 + 1];

    float s[8];
#pragma unroll
    for (int e = 0; e < 8; e++) {
        const float4* rwp = (const float4*)(g_relWr + rr[e] * HDIM);
        const float4* rqp = (const float4*)(g_relWqr + qq[e] * HDIM);
        const __half2* nh2 = (const __half2*)&nv[e];
        float acc = 0.f;
        {
            float4 b = rwp[lane * 2], c = rqp[lane * 2];
            float2 n01 = __half22float2(nh2[0]);
            float2 n23 = __half22float2(nh2[1]);
            float f0 = fmaxf(n01.x + b.x + c.x + bq0.x, 0.f);
            float f1 = fmaxf(n01.y + b.y + c.y + bq0.y, 0.f);
            float f2 = fmaxf(n23.x + b.z + c.z + bq0.z, 0.f);
            float f3 = fmaxf(n23.y + b.w + c.w + bq0.w, 0.f);
            acc = fmaf(f0, wa0.x, acc); acc = fmaf(f1, wa0.y, acc);
            acc = fmaf(f2, wa0.z, acc); acc = fmaf(f3, wa0.w, acc);
        }
        {
            float4 b = rwp[lane * 2 + 1], c = rqp[lane * 2 + 1];
            float2 n01 = __half22float2(nh2[2]);
            float2 n23 = __half22float2(nh2[3]);
            float f0 = fmaxf(n01.x + b.x + c.x + bq1.x, 0.f);
            float f1 = fmaxf(n01.y + b.y + c.y + bq1.y, 0.f);
            float f2 = fmaxf(n23.x + b.z + c.z + bq1.z, 0.f);
            float f3 = fmaxf(n23.y + b.w + c.w + bq1.w, 0.f);
            acc = fmaf(f0, wa1.x, acc); acc = fmaf(f1, wa1.y, acc);
            acc = fmaf(f2, wa1.z, acc); acc = fmaf(f3, wa1.w, acc);
        }
        s[e] = acc;
    }
#pragma unroll
    for (int o = 16; o > 0; o >>= 1) {
#pragma unroll
        for (int e = 0; e < 8; e++)
            s[e] += __shfl_xor_sync(0xffffffffu, s[e], o);
    }
    if (lane < 8) {
        float sv = s[0];
#pragma unroll
        for (int e = 1; e < 8; e++) sv = (lane == e) ? s[e] : sv;
        g_alpha[m0 + lane] = 1.f / (1.f + __expf(-(sv + b_alpha[0])));
    }
}

// ---------------- CSR aggregation: warp/node, fp16 sources ----------------
__global__ __launch_bounds__(256)
void agg_kernel(const int* __restrict__ erel,
                const int* __restrict__ tent)
{
    const int n = blockIdx.x * 8 + (threadIdx.x >> 5);
    if (n >= NNEW) return;
    const int lane = threadIdx.x & 31;
    const int s0 = g_rowptr[n], e0 = g_rowptr[n + 1];

    float4 acc0 = make_float4(0.f, 0.f, 0.f, 0.f);
    float4 acc1 = make_float4(0.f, 0.f, 0.f, 0.f);
    for (int i = s0; i < e0; i += 4) {
        const int cnt = min(4, e0 - i);
        int mm[4];
#pragma unroll
        for (int j = 0; j < 4; j++)
            if (j < cnt) mm[j] = g_colidx[i + j];
        float aa[4]; int rr[4]; uint2 tv[4];
#pragma unroll
        for (int j = 0; j < 4; j++) {
            if (j < cnt) {
                aa[j] = g_alpha[mm[j]];
                rr[j] = erel[mm[j]];
                int te = tent[mm[j]];
                tv[j] = *(const uint2*)(g_entH + (size_t)te * EDIM + lane * 4);
            }
        }
#pragma unroll
        for (int j = 0; j < 4; j++) {
            if (j < cnt) {
                const float4 hv = unpack_h(*(const uint2*)(g_relH + rr[j] * EDIM + lane * 4));
                const float4 tvf = unpack_h(tv[j]);
                const float a = aa[j];
                acc0.x = fmaf(a, hv.x, acc0.x); acc0.y = fmaf(a, hv.y, acc0.y);
                acc0.z = fmaf(a, hv.z, acc0.z); acc0.w = fmaf(a, hv.w, acc0.w);
                acc1.x = fmaf(a, tvf.x, acc1.x); acc1.y = fmaf(a, tvf.y, acc1.y);
                acc1.z = fmaf(a, tvf.z, acc1.z); acc1.w = fmaf(a, tvf.w, acc1.w);
            }
        }
    }
    __half* aggp = g_agg + (size_t)n * (2 * EDIM);
    *(uint2*)&aggp[lane * 4]        = pack_h(acc0);
    *(uint2*)&aggp[EDIM + lane * 4] = pack_h(acc1);
}

// ---------------- GRU gates + LayerNorm: warp per node ----------------
__global__ __launch_bounds__(256)
void gru_ln_kernel(const float* __restrict__ ln_g, const float* __restrict__ ln_b)
{
    const int n = blockIdx.x * 8 + (threadIdx.x >> 5);
    if (n >= NNEW) return;
    const int lane = threadIdx.x & 31;
    const __half* GX = g_GX + (size_t)n * 3 * HDIM;
    const __half* GH = g_GH + (size_t)n * 3 * HDIM;
    const int c0 = lane * 8;

    uint4 xr4 = *(const uint4*)(GX + c0);
    uint4 xz4 = *(const uint4*)(GX + HDIM + c0);
    uint4 xn4 = *(const uint4*)(GX + 2 * HDIM + c0);
    uint4 hr4 = *(const uint4*)(GH + c0);
    uint4 hz4 = *(const uint4*)(GH + HDIM + c0);
    uint4 hn4 = *(const uint4*)(GH + 2 * HDIM + c0);
    uint4 hp4 = *(const uint4*)(g_hprev + (size_t)n * HDIM + c0);

    const __half2* xr2 = (const __half2*)&xr4;
    const __half2* xz2 = (const __half2*)&xz4;
    const __half2* xn2 = (const __half2*)&xn4;
    const __half2* hr2 = (const __half2*)&hr4;
    const __half2* hz2 = (const __half2*)&hz4;
    const __half2* hn2 = (const __half2*)&hn4;
    const __half2* hp2 = (const __half2*)&hp4;

    float h[8];
    float s1 = 0.f, s2 = 0.f;
#pragma unroll
    for (int p = 0; p < 4; p++) {
        float2 xr = __half22float2(xr2[p]);
        float2 xz = __half22float2(xz2[p]);
        float2 xn = __half22float2(xn2[p]);
        float2 hr = __half22float2(hr2[p]);
        float2 hz = __half22float2(hz2[p]);
        float2 hn = __half22float2(hn2[p]);
        float2 hp = __half22float2(hp2[p]);
        float rg0 = 1.f / (1.f + __expf(-(xr.x + hr.x)));
        float rg1 = 1.f / (1.f + __expf(-(xr.y + hr.y)));
        float zg0 = 1.f / (1.f + __expf(-(xz.x + hz.x)));
        float zg1 = 1.f / (1.f + __expf(-(xz.y + hz.y)));
        float ng0 = tanhf(xn.x + rg0 * hn.x);
        float ng1 = tanhf(xn.y + rg1 * hn.y);
        h[p * 2]     = (1.f - zg0) * ng0 + zg0 * hp.x;
        h[p * 2 + 1] = (1.f - zg1) * ng1 + zg1 * hp.y;
        s1 += h[p * 2] + h[p * 2 + 1];
        s2 += h[p * 2] * h[p * 2] + h[p * 2 + 1] * h[p * 2 + 1];
    }
#pragma unroll
    for (int o = 16; o > 0; o >>= 1) {
        s1 += __shfl_xor_sync(0xffffffffu, s1, o);
        s2 += __shfl_xor_sync(0xffffffffu, s2, o);
    }
    const float mu  = s1 * (1.f / HDIM);
    const float var = s2 * (1.f / HDIM) - mu * mu;
    const float inv = rsqrtf(var + 1e-5f);

    const float4 g0 = ((const float4*)ln_g)[lane * 2];
    const float4 g1 = ((const float4*)ln_g)[lane * 2 + 1];
    const float4 b0 = ((const float4*)ln_b)[lane * 2];
    const float4 b1 = ((const float4*)ln_b)[lane * 2 + 1];

    float4 o0, o1;
    o0.x = (h[0] - mu) * inv * g0.x + b0.x;
    o0.y = (h[1] - mu) * inv * g0.y + b0.y;
    o0.z = (h[2] - mu) * inv * g0.z + b0.z;
    o0.w = (h[3] - mu) * inv * g0.w + b0.w;
    o1.x = (h[4] - mu) * inv * g1.x + b1.x;
    o1.y = (h[5] - mu) * inv * g1.y + b1.y;
    o1.z = (h[6] - mu) * inv * g1.z + b1.z;
    o1.w = (h[7] - mu) * inv * g1.w + b1.w;

    uint4 outv;
    uint2 p0 = pack_h(o0), p1 = pack_h(o1);
    outv.x = p0.x; outv.y = p0.y; outv.z = p1.x; outv.w = p1.y;
    *(uint4*)(g_hnew + (size_t)n * HDIM + c0) = outv;
}

// ---------------- final scoring: 8 edges per warp ----------------
__global__ __launch_bounds__(256)
void edge_score(const int* __restrict__ erel,
                const int* __restrict__ tent,
                const int* __restrict__ tnode,
                const int* __restrict__ bidx,
                const float* __restrict__ rankW,
                const float* __restrict__ rank_b,
                float* __restrict__ out)
{
    const int m0 = (blockIdx.x * 8 + (threadIdx.x >> 5)) * 8;
    if (m0 >= MEDGE) return;
    const int lane = threadIdx.x & 31;

    int rr[8], te[8], tt[8];
    float qd[8];
#pragma unroll
    for (int e = 0; e < 8; e++) {
        rr[e] = erel[m0 + e]; te[e] = tent[m0 + e]; tt[e] = tnode[m0 + e];
        qd[e] = g_qdot[bidx[m0 + e]];
    }
    uint4 ev[8], hv[8];
#pragma unroll
    for (int e = 0; e < 8; e++) {
        ev[e] = ((const uint4*)(g_EW1 + (size_t)te[e] * HDIM))[lane];
        hv[e] = ((const uint4*)(g_HN3 + (size_t)tt[e] * HDIM))[lane];
    }
    const float4 w0 = ((const float4*)rankW)[lane * 2];
    const float4 w1 = ((const float4*)rankW)[lane * 2 + 1];

    float s[8];
#pragma unroll
    for (int e = 0; e < 8; e++) {
        const uint4 cv = ((const uint4*)(g_relC2h + rr[e] * HDIM))[lane];
        const __half2* e2 = (const __half2*)&ev[e];
        const __half2* h2 = (const __half2*)&hv[e];
        const __half2* c2 = (const __half2*)&cv;
        float acc = 0.f;
        float2 a01 = __half22float2(e2[0]), a23 = __half22float2(e2[1]);
        float2 d01 = __half22float2(h2[0]), d23 = __half22float2(h2[1]);
        float2 c01 = __half22float2(c2[0]), c23 = __half22float2(c2[1]);
        float v0 = a01.x + c01.x + d01.x; v0 = (v0 > 0.f) ? v0 : 0.01f * v0;
        float v1 = a01.y + c01.y + d01.y; v1 = (v1 > 0.f) ? v1 : 0.01f * v1;
        float v2 = a23.x + c23.x + d23.x; v2 = (v2 > 0.f) ? v2 : 0.01f * v2;
        float v3 = a23.y + c23.y + d23.y; v3 = (v3 > 0.f) ? v3 : 0.01f * v3;
        acc = fmaf(v0, w0.x, acc); acc = fmaf(v1, w0.y, acc);
        acc = fmaf(v2, w0.z, acc); acc = fmaf(v3, w0.w, acc);
        a01 = __half22float2(e2[2]); a23 = __half22float2(e2[3]);
        d01 = __half22float2(h2[2]); d23 = __half22float2(h2[3]);
        c01 = __half22float2(c2[2]); c23 = __half22float2(c2[3]);
        v0 = a01.x + c01.x + d01.x; v0 = (v0 > 0.f) ? v0 : 0.01f * v0;
        v1 = a01.y + c01.y + d01.y; v1 = (v1 > 0.f) ? v1 : 0.01f * v1;
        v2 = a23.x + c23.x + d23.x; v2 = (v2 > 0.f) ? v2 : 0.01f * v2;
        v3 = a23.y + c23.y + d23.y; v3 = (v3 > 0.f) ? v3 : 0.01f * v3;
        acc = fmaf(v0, w1.x, acc); acc = fmaf(v1, w1.y, acc);
        acc = fmaf(v2, w1.z, acc); acc = fmaf(v3, w1.w, acc);
        s[e] = acc;
    }
#pragma unroll
    for (int o = 16; o > 0; o >>= 1) {
#pragma unroll
        for (int e = 0; e < 8; e++)
            s[e] += __shfl_xor_sync(0xffffffffu, s[e], o);
    }
    if (lane < 8) {
        float sv = s[0], qv = qd[0];
#pragma unroll
        for (int e = 1; e < 8; e++) {
            sv = (lane == e) ? s[e] : sv;
            qv = (lane == e) ? qd[e] : qv;
        }
        out[m0 + lane] = sv + qv + rank_b[0];
    }
}

// ---------------- launcher ----------------
extern "C" void kernel_launch(void* const* d_in, const int* in_sizes, int n_in,
                              void* d_out, int out_size)
{
    const float* entity_emb   = (const float*)d_in[0];
    const float* relation_emb = (const float*)d_in[1];
    const float* node_hidden  = (const float*)d_in[2];
    const float* query_repr   = (const float*)d_in[3];
    const float* Ws           = (const float*)d_in[4];
    const float* Wr           = (const float*)d_in[5];
    const float* Wqr          = (const float*)d_in[6];
    const float* bqr          = (const float*)d_in[7];
    const float* w_alpha      = (const float*)d_in[8];
    const float* b_alpha      = (const float*)d_in[9];
    const float* W_ih         = (const float*)d_in[10];
    const float* W_hh         = (const float*)d_in[11];
    const float* b_ih         = (const float*)d_in[12];
    const float* b_hh         = (const float*)d_in[13];
    const float* We2h_W       = (const float*)d_in[14];
    const float* We2h_b       = (const float*)d_in[15];
    const float* cand_W       = (const float*)d_in[16];
    const float* cand_b       = (const float*)d_in[17];
    const float* rank_W       = (const float*)d_in[18];
    const float* rank_b       = (const float*)d_in[19];
    const float* ln_g         = (const float*)d_in[20];
    const float* ln_b         = (const float*)d_in[21];
    const int* head_node      = (const int*)d_in[22];
    const int* edge_rel       = (const int*)d_in[23];
    const int* tail_ent       = (const int*)d_in[24];
    const int* tail_node      = (const int*)d_in[25];
    const int* query_rel      = (const int*)d_in[26];
    const int* batch_idx      = (const int*)d_in[27];
    const int* tail_node_ent  = (const int*)d_in[28];
    float* scores = (float*)d_out;

    __half *p_NHW, *p_EW1, *p_GX, *p_GH, *p_HN3, *p_hprev, *p_hnew, *p_agg, *p_entH;
    float *p_WsT, *p_We2hT, *p_c1T, *p_c3T;
    cudaGetSymbolAddress((void**)&p_NHW,   g_NHW);
    cudaGetSymbolAddress((void**)&p_EW1,   g_EW1);
    cudaGetSymbolAddress((void**)&p_agg,   g_agg);
    cudaGetSymbolAddress((void**)&p_hprev, g_hprev);
    cudaGetSymbolAddress((void**)&p_GX,    g_GX);
    cudaGetSymbolAddress((void**)&p_GH,    g_GH);
    cudaGetSymbolAddress((void**)&p_hnew,  g_hnew);
    cudaGetSymbolAddress((void**)&p_HN3,   g_HN3);
    cudaGetSymbolAddress((void**)&p_entH,  g_entH);
    cudaGetSymbolAddress((void**)&p_WsT,   g_WsT);
    cudaGetSymbolAddress((void**)&p_We2hT, g_We2hT);
    cudaGetSymbolAddress((void**)&p_c1T,   g_c1T);
    cudaGetSymbolAddress((void**)&p_c3T,   g_c3T);

    cudaFuncSetAttribute(hmma_gemm<0, false, true , false>, cudaFuncAttributeMaxDynamicSharedMemorySize, GEMM_DSMEM);
    cudaFuncSetAttribute(hmma_gemm<1, false, true , true >, cudaFuncAttributeMaxDynamicSharedMemorySize, GEMM_DSMEM);
    cudaFuncSetAttribute(hmma_gemm<0, false, true , true >, cudaFuncAttributeMaxDynamicSharedMemorySize, GEMM_DSMEM);
    cudaFuncSetAttribute(hmma_gemm<2, true , true , false>, cudaFuncAttributeMaxDynamicSharedMemorySize, GEMM_DSMEM);

    static cudaStream_t s1 = nullptr, s2 = nullptr;
    static cudaEvent_t evStart = nullptr, evPre = nullptr, evGH = nullptr,
                       evEW1 = nullptr, evCSR = nullptr, evRel = nullptr;
    if (s1 == nullptr) {
        cudaStreamCreateWithFlags(&s1, cudaStreamNonBlocking);
        cudaStreamCreateWithFlags(&s2, cudaStreamNonBlocking);
        cudaEventCreateWithFlags(&evStart, cudaEventDisableTiming);
        cudaEventCreateWithFlags(&evPre, cudaEventDisableTiming);
        cudaEventCreateWithFlags(&evGH, cudaEventDisableTiming);
        cudaEventCreateWithFlags(&evEW1, cudaEventDisableTiming);
        cudaEventCreateWithFlags(&evCSR, cudaEventDisableTiming);
        cudaEventCreateWithFlags(&evRel, cudaEventDisableTiming);
    }

    // ---- fork point ----
    cudaEventRecord(evStart, 0);

    // ---- s2: entity fp16 convert, then CSR build (fast 3-phase scan) ----
    cudaStreamWaitEvent(s2, evStart, 0);
    ent_convert_kernel<<<(NENT * EDIM / 4 + 255) / 256, 256, 0, s2>>>(entity_emb);
    csr_zero_kernel<<<(NNEW + 255) / 256, 256, 0, s2>>>();
    csr_hist_kernel<<<(MEDGE + 255) / 256, 256, 0, s2>>>(tail_node);
    csr_scan1_kernel<<<NBLK, SCAN_BLK, 0, s2>>>();
    csr_scan2_kernel<<<1, SCAN_BLK, 0, s2>>>();
    csr_scan3_kernel<<<(NNEW + 255) / 256, 256, 0, s2>>>();
    csr_fill_kernel<<<(MEDGE + 255) / 256, 256, 0, s2>>>(tail_node);
    cudaEventRecord(evCSR, s2);

    // ---- s1: rel tables + qdot + rel fp16 ----
    cudaStreamWaitEvent(s1, evStart, 0);
    rel_precompute<<<NREL, 256, 0, s1>>>(relation_emb, Wr, Wqr, cand_W, cand_b);
    qdot_kernel<<<BDIM / 8, 256, 0, s1>>>(query_repr, rank_W);
    rel_convert_kernel<<<(NREL * EDIM / 4 + 255) / 256, 256, 0, s1>>>(relation_emb);
    cudaEventRecord(evRel, s1);

    // ---- main stream: weight transposes ----
    {
        TransJob j0 = {Ws, p_WsT, HDIM, HDIM};
        TransJob j1 = {We2h_W, p_We2hT, EDIM, HDIM};
        TransJob j2 = {cand_W, p_c1T, EDIM, HDIM};
        TransJob j3 = {cand_W + 2 * EDIM * HDIM, p_c3T, HDIM, HDIM};
        transpose4_kernel<<<dim3(HDIM / 32, HDIM / 32, 4), 256>>>(j0, j1, j2, j3);
    }
    cudaEventRecord(evPre, 0);

    // ---- s1 (after prep): hprev -> GH ----
    cudaStreamWaitEvent(s1, evPre, 0);
    hmma_gemm<2, true, true, false><<<dim3(2, (NNEW + 127) / 128), 256, GEMM_DSMEM, s1>>>(
        entity_emb, p_We2hT, We2h_b, p_hprev, NNEW, HDIM, EDIM, tail_node_ent);
    hmma_gemm<1, false, true, true><<<dim3(6, (NNEW + 127) / 128), 256, GEMM_DSMEM, s1>>>(
        p_hprev, W_hh, b_hh, p_GH, NNEW, 3 * HDIM, HDIM, nullptr);
    cudaEventRecord(evGH, s1);

    // ---- s2 (after convert+CSR): EW1 from fp16 entity ----
    cudaStreamWaitEvent(s2, evPre, 0);
    hmma_gemm<0, false, true, true><<<dim3(2, (NENT + 127) / 128), 256, GEMM_DSMEM, s2>>>(
        p_entH, p_c1T, nullptr, p_EW1, NENT, HDIM, EDIM, nullptr);
    cudaEventRecord(evEW1, s2);

    // ---- main: NHW -> alpha -> agg -> GX ----
    hmma_gemm<0, false, true, false><<<dim3(2, (NNODES + 127) / 128), 256, GEMM_DSMEM>>>(
        node_hidden, p_WsT, nullptr, p_NHW, NNODES, HDIM, HDIM, nullptr);
    cudaStreamWaitEvent(0, evRel, 0);
    alpha_kernel<<<(MEDGE / 8 + 7) / 8, 256>>>(
        bqr, w_alpha, b_alpha, head_node, edge_rel, query_rel);
    cudaStreamWaitEvent(0, evCSR, 0);
    agg_kernel<<<(NNEW + 7) / 8, 256>>>(edge_rel, tail_ent);
    hmma_gemm<1, false, true, true><<<dim3(6, (NNEW + 127) / 128), 256, GEMM_DSMEM>>>(
        p_agg, W_ih, b_ih, p_GX, NNEW, 3 * HDIM, 2 * EDIM, nullptr);

    // ---- join GH, GRU+LN, HN3 ----
    cudaStreamWaitEvent(0, evGH, 0);
    gru_ln_kernel<<<(NNEW + 7) / 8, 256>>>(ln_g, ln_b);
    hmma_gemm<0, false, true, true><<<dim3(2, (NNEW + 127) / 128), 256, GEMM_DSMEM>>>(
        p_hnew, p_c3T, nullptr, p_HN3, NNEW, HDIM, HDIM, nullptr);

    // ---- join EW1, final scores ----
    cudaStreamWaitEvent(0, evEW1, 0);
    edge_score<<<(MEDGE / 8 + 7) / 8, 256>>>(
        edge_rel, tail_ent, tail_node, batch_idx, rank_W, rank_b, scores);
}

// round 16
// speedup vs baseline: 1.0179x; 1.0179x over previous
#include <cuda_runtime.h>
#include <cuda_fp16.h>
#include <math.h>
#include <stdint.h>

// ---------------- problem constants ----------------
#define NENT   200000
#define NREL   500
#define NNODES 100000
#define NNEW   50000
#define MEDGE  200000
#define EDIM   128
#define HDIM   256
#define QDIM   256
#define BDIM   256
#define SCAN_BLK 256
#define NBLK ((NNEW + SCAN_BLK - 1) / SCAN_BLK)   // 196

// ---------------- device scratch (no allocations allowed) ----------------
__device__ __align__(16) __half g_relWrh [NREL * HDIM];   // fp16 now
__device__ __align__(16) __half g_relWqrh[NREL * HDIM];   // fp16 now
__device__ __align__(16) __half g_relC2h[NREL * HDIM];
__device__ __align__(16) float  g_qdot  [BDIM];
__device__ __align__(16) __half g_NHW   [(size_t)NNODES * HDIM];
__device__ __align__(16) __half g_EW1   [(size_t)NENT   * HDIM];
__device__ __align__(16) __half g_agg   [(size_t)NNEW * 2 * EDIM];
__device__ __align__(16) __half g_hprev [(size_t)NNEW * HDIM];
__device__ __align__(16) __half g_GX    [(size_t)NNEW * 3 * HDIM];
__device__ __align__(16) __half g_GH    [(size_t)NNEW * 3 * HDIM];
__device__ __align__(16) __half g_hnew  [(size_t)NNEW * HDIM];
__device__ __align__(16) __half g_HN3   [(size_t)NNEW * HDIM];
// fp16 copies of source embeddings
__device__ __align__(16) __half g_entH  [(size_t)NENT * EDIM];
__device__ __align__(16) __half g_relH  [NREL * EDIM];
// transposed weights [N, K]
__device__ __align__(16) float  g_WsT   [HDIM * HDIM];
__device__ __align__(16) float  g_We2hT [HDIM * EDIM];
__device__ __align__(16) float  g_c1T   [HDIM * EDIM];
__device__ __align__(16) float  g_c3T   [HDIM * HDIM];
// CSR for tail_node aggregation
__device__ int   g_cnt   [NNEW];
__device__ int   g_rowptr[NNEW + 1];
__device__ int   g_colidx[MEDGE];
__device__ float g_alpha [MEDGE];
__device__ int   g_bsum  [NBLK];
__device__ int   g_boff  [NBLK];

// ---------------- helpers ----------------
__device__ __forceinline__ uint32_t smem_u32(const void* p) {
    uint32_t a;
    asm("{ .reg .u64 t; cvta.to.shared.u64 t, %1; cvt.u32.u64 %0, t; }" : "=r"(a) : "l"(p));
    return a;
}

__device__ __forceinline__ void ldmx4(uint32_t addr, uint32_t& r0, uint32_t& r1,
                                      uint32_t& r2, uint32_t& r3) {
    asm volatile("ldmatrix.sync.aligned.m8n8.x4.shared.b16 {%0,%1,%2,%3}, [%4];"
                 : "=r"(r0), "=r"(r1), "=r"(r2), "=r"(r3) : "r"(addr));
}

__device__ __forceinline__ void mma16816(float* c, const uint32_t* a,
                                         uint32_t b0, uint32_t b1) {
    asm volatile(
        "mma.sync.aligned.m16n8k16.row.col.f32.f16.f16.f32 "
        "{%0,%1,%2,%3}, {%4,%5,%6,%7}, {%8,%9}, {%0,%1,%2,%3};"
        : "+f"(c[0]), "+f"(c[1]), "+f"(c[2]), "+f"(c[3])
        : "r"(a[0]), "r"(a[1]), "r"(a[2]), "r"(a[3]), "r"(b0), "r"(b1));
}

__device__ __forceinline__ uint2 pack_h(float4 v) {
    __half2 h01; h01.x = __float2half_rn(v.x); h01.y = __float2half_rn(v.y);
    __half2 h23; h23.x = __float2half_rn(v.z); h23.y = __float2half_rn(v.w);
    return make_uint2(*(uint32_t*)&h01, *(uint32_t*)&h23);
}

__device__ __forceinline__ float4 unpack_h(uint2 u) {
    __half2 h01 = *(__half2*)&u.x;
    __half2 h23 = *(__half2*)&u.y;
    float2 a = __half22float2(h01), b = __half22float2(h23);
    return make_float4(a.x, a.y, b.x, b.y);
}

// ---------------- pipelined HMMA fp16 GEMM ----------------
#define ASTRIDE 40
#define TILE_B  (128 * ASTRIDE * 2)
#define STAGE_B (2 * TILE_B)
#define GEMM_DSMEM (2 * STAGE_B)

template <int EPI, bool GATHER, bool OUTH, bool INH>
__global__ __launch_bounds__(256, 2)
void hmma_gemm(const void* __restrict__ Av, const float* __restrict__ Bt,
               const float* __restrict__ bias, void* __restrict__ Cv,
               int M, int N, int K, const int* __restrict__ gidx)
{
    extern __shared__ char dsm[];
    const uint32_t sb = smem_u32(dsm);

    const int tid = threadIdx.x;
    const int wid = tid >> 5, lane = tid & 31;
    const int bx = blockIdx.x, by = blockIdx.y;
    const int wm = (wid & 3) * 32;
    const int wn = (wid >> 2) * 64;

    float acc[2][8][4];
#pragma unroll
    for (int i = 0; i < 2; i++)
#pragma unroll
        for (int j = 0; j < 8; j++)
#pragma unroll
            for (int u = 0; u < 4; u++) acc[i][j][u] = 0.f;

    const float*  aF[4]; const __half* aHp[4];
    bool av[4]; int soff[4];
    const float* bptr[4];
#pragma unroll
    for (int i = 0; i < 4; i++) {
        int idx = tid + 256 * i;
        int row = idx >> 3, c4 = (idx & 7) * 4;
        int grow = by * 128 + row;
        av[i] = (grow < M);
        size_t phys = 0;
        if (av[i]) phys = GATHER ? (size_t)gidx[grow] : (size_t)grow;
        if (INH) aHp[i] = (const __half*)Av + phys * (size_t)K + c4;
        else     aF[i]  = (const float*)Av + phys * (size_t)K + c4;
        bptr[i] = Bt + (size_t)(bx * 128 + row) * K + c4;
        soff[i] = (row * ASTRIDE + c4) * 2;
    }

    const int lrow = lane & 15;
    const int lk   = (lane >> 4) << 3;
    const uint32_t aoffH = (uint32_t)((wm + lrow) * ASTRIDE + lk) * 2;
    const int brow = (lane & 7) + ((lane >> 4) << 3);
    const int bk   = ((lane >> 3) & 1) << 3;
    const uint32_t boffH = (uint32_t)((wn + brow) * ASTRIDE + bk) * 2;

    const int KT = K >> 5;

    float4 ra[4]; uint2 rah[4]; float4 rb[4];
#pragma unroll
    for (int i = 0; i < 4; i++) {
        if (INH) rah[i] = av[i] ? *(const uint2*)(aHp[i]) : make_uint2(0u, 0u);
        else     ra[i]  = av[i] ? *(const float4*)(aF[i]) : make_float4(0.f, 0.f, 0.f, 0.f);
        rb[i] = *(const float4*)(bptr[i]);
    }

    for (int t = 0; t < KT; t++) {
        const uint32_t stg = (uint32_t)(t & 1) * STAGE_B;
        char* base = dsm + stg;
#pragma unroll
        for (int i = 0; i < 4; i++) {
            *(uint2*)(base + soff[i])          = INH ? rah[i] : pack_h(ra[i]);
            *(uint2*)(base + TILE_B + soff[i]) = pack_h(rb[i]);
        }
        __syncthreads();

        if (t + 1 < KT) {
            const int koff = (t + 1) * 32;
#pragma unroll
            for (int i = 0; i < 4; i++) {
                if (INH) rah[i] = av[i] ? *(const uint2*)(aHp[i] + koff) : make_uint2(0u, 0u);
                else     ra[i]  = av[i] ? *(const float4*)(aF[i] + koff)
                                        : make_float4(0.f, 0.f, 0.f, 0.f);
                rb[i] = *(const float4*)(bptr[i] + koff);
            }
        }

        const uint32_t aH = sb + stg + aoffH;
        const uint32_t bH = sb + stg + TILE_B + boffH;

#pragma unroll
        for (int ks = 0; ks < 32; ks += 16) {
            uint32_t ah[2][4];
#pragma unroll
            for (int mi = 0; mi < 2; mi++) {
                uint32_t off = (uint32_t)(mi * 16 * ASTRIDE + ks) * 2;
                ldmx4(aH + off, ah[mi][0], ah[mi][1], ah[mi][2], ah[mi][3]);
            }
#pragma unroll
            for (int nj = 0; nj < 4; nj++) {
                uint32_t off = (uint32_t)(nj * 16 * ASTRIDE + ks) * 2;
                uint32_t bh[4];
                ldmx4(bH + off, bh[0], bh[1], bh[2], bh[3]);
#pragma unroll
                for (int mi = 0; mi < 2; mi++) {
#pragma unroll
                    for (int h = 0; h < 2; h++)
                        mma16816(acc[mi][nj * 2 + h], ah[mi], bh[h * 2], bh[h * 2 + 1]);
                }
            }
        }
    }

    const int g = lane >> 2, tig = lane & 3;
#pragma unroll
    for (int mi = 0; mi < 2; mi++) {
        const int r0 = by * 128 + wm + mi * 16 + g;
        const int r1 = r0 + 8;
#pragma unroll
        for (int nj = 0; nj < 8; nj++) {
            const int col = bx * 128 + wn + nj * 8 + 2 * tig;
            float b0 = 0.f, b1 = 0.f;
            if (EPI >= 1) { b0 = bias[col]; b1 = bias[col + 1]; }
            float* c = acc[mi][nj];
            float x0 = c[0], x1 = c[1], x2 = c[2], x3 = c[3];
            if (EPI >= 1) { x0 += b0; x1 += b1; x2 += b0; x3 += b1; }
            if (EPI == 2) {
                x0 = (x0 > 0.f) ? x0 : 0.01f * x0;
                x1 = (x1 > 0.f) ? x1 : 0.01f * x1;
                x2 = (x2 > 0.f) ? x2 : 0.01f * x2;
                x3 = (x3 > 0.f) ? x3 : 0.01f * x3;
            }
            if (OUTH) {
                __half* Ch = (__half*)Cv;
                if (r0 < M) {
                    __half2 p; p.x = __float2half_rn(x0); p.y = __float2half_rn(x1);
                    *(uint32_t*)&Ch[(size_t)r0 * N + col] = *(uint32_t*)&p;
                }
                if (r1 < M) {
                    __half2 p; p.x = __float2half_rn(x2); p.y = __float2half_rn(x3);
                    *(uint32_t*)&Ch[(size_t)r1 * N + col] = *(uint32_t*)&p;
                }
            } else {
                float* Cf = (float*)Cv;
                if (r0 < M) *(float2*)&Cf[(size_t)r0 * N + col] = make_float2(x0, x1);
                if (r1 < M) *(float2*)&Cf[(size_t)r1 * N + col] = make_float2(x2, x3);
            }
        }
    }
}

// ---------------- fused weight transposes ----------------
struct TransJob { const float* in; float* out; int K; int N; };

__global__ void transpose4_kernel(TransJob j0, TransJob j1, TransJob j2, TransJob j3)
{
    TransJob jb = (blockIdx.z == 0) ? j0 : (blockIdx.z == 1) ? j1
                 : (blockIdx.z == 2) ? j2 : j3;
    const int k0 = blockIdx.y * 32;
    if (k0 >= jb.K) return;
    __shared__ float t[32][33];
    const int tx = threadIdx.x & 31, ty = threadIdx.x >> 5;
    const int n0 = blockIdx.x * 32;
#pragma unroll
    for (int i = 0; i < 32; i += 8)
        t[ty + i][tx] = jb.in[(size_t)(k0 + ty + i) * jb.N + n0 + tx];
    __syncthreads();
#pragma unroll
    for (int i = 0; i < 32; i += 8)
        jb.out[(size_t)(n0 + ty + i) * jb.K + k0 + tx] = t[tx][ty + i];
}

// ---------------- fp16 conversions of source embeddings ----------------
__global__ void ent_convert_kernel(const float* __restrict__ e)
{
    size_t i = (size_t)blockIdx.x * blockDim.x + threadIdx.x;
    if (i < (size_t)NENT * EDIM / 4)
        ((uint2*)g_entH)[i] = pack_h(((const float4*)e)[i]);
}

__global__ void rel_convert_kernel(const float* __restrict__ r)
{
    size_t i = (size_t)blockIdx.x * blockDim.x + threadIdx.x;
    if (i < (size_t)NREL * EDIM / 4)
        ((uint2*)g_relH)[i] = pack_h(((const float4*)r)[i]);
}

// ---------------- small precompute kernels ----------------
__global__ void rel_precompute(const float* __restrict__ rel_emb,
                               const float* __restrict__ Wr,
                               const float* __restrict__ Wqr,
                               const float* __restrict__ candW,
                               const float* __restrict__ cand_b)
{
    const int r = blockIdx.x;
    const int j = threadIdx.x;
    __shared__ float re[EDIM];
    if (j < EDIM) re[j] = rel_emb[r * EDIM + j];
    __syncthreads();
    float s1 = 0.f, s2 = 0.f, s3 = 0.f;
#pragma unroll 4
    for (int k = 0; k < EDIM; k++) {
        const float rv = re[k];
        s1 = fmaf(rv, Wr[k * HDIM + j], s1);
        s2 = fmaf(rv, Wqr[k * HDIM + j], s2);
        s3 = fmaf(rv, candW[(EDIM + k) * HDIM + j], s3);
    }
    g_relWrh[r * HDIM + j]  = __float2half_rn(s1);
    g_relWqrh[r * HDIM + j] = __float2half_rn(s2);
    g_relC2h[r * HDIM + j]  = __float2half_rn(s3 + cand_b[j]);
}

__global__ void qdot_kernel(const float* __restrict__ qrep,
                            const float* __restrict__ rankW)
{
    const int b = blockIdx.x * 8 + (threadIdx.x >> 5);
    const int lane = threadIdx.x & 31;
    if (b >= BDIM) return;
    float s = 0.f;
#pragma unroll
    for (int i = 0; i < 8; i++) {
        int q = lane + 32 * i;
        s = fmaf(qrep[b * QDIM + q], rankW[HDIM + q], s);
    }
#pragma unroll
    for (int o = 16; o > 0; o >>= 1) s += __shfl_xor_sync(0xffffffffu, s, o);
    if (lane == 0) g_qdot[b] = s;
}

// ---------------- CSR build ----------------
__global__ void csr_zero_kernel()
{
    int i = blockIdx.x * blockDim.x + threadIdx.x;
    if (i < NNEW) g_cnt[i] = 0;
}

__global__ void csr_hist_kernel(const int* __restrict__ tnode)
{
    int m = blockIdx.x * blockDim.x + threadIdx.x;
    if (m < MEDGE) atomicAdd(&g_cnt[tnode[m]], 1);
}

__global__ __launch_bounds__(SCAN_BLK)
void csr_scan1_kernel()
{
    __shared__ int sh[SCAN_BLK];
    const int i = blockIdx.x * SCAN_BLK + threadIdx.x;
    const int v = (i < NNEW) ? g_cnt[i] : 0;
    sh[threadIdx.x] = v;
    __syncthreads();
#pragma unroll
    for (int off = 1; off < SCAN_BLK; off <<= 1) {
        int t = (threadIdx.x >= off) ? sh[threadIdx.x - off] : 0;
        __syncthreads();
        sh[threadIdx.x] += t;
        __syncthreads();
    }
    if (i < NNEW) g_rowptr[i] = sh[threadIdx.x] - v;
    if (threadIdx.x == SCAN_BLK - 1) g_bsum[blockIdx.x] = sh[threadIdx.x];
}

__global__ __launch_bounds__(SCAN_BLK)
void csr_scan2_kernel()
{
    __shared__ int sh[SCAN_BLK];
    const int v = (threadIdx.x < NBLK) ? g_bsum[threadIdx.x] : 0;
    sh[threadIdx.x] = v;
    __syncthreads();
#pragma unroll
    for (int off = 1; off < SCAN_BLK; off <<= 1) {
        int t = (threadIdx.x >= off) ? sh[threadIdx.x - off] : 0;
        __syncthreads();
        sh[threadIdx.x] += t;
        __syncthreads();
    }
    if (threadIdx.x < NBLK) g_boff[threadIdx.x] = sh[threadIdx.x] - v;
}

__global__ void csr_scan3_kernel()
{
    int i = blockIdx.x * blockDim.x + threadIdx.x;
    if (i < NNEW) {
        g_rowptr[i] += g_boff[i / SCAN_BLK];
        g_cnt[i] = 0;
    }
    if (i == 0) g_rowptr[NNEW] = MEDGE;
}

__global__ void csr_fill_kernel(const int* __restrict__ tnode)
{
    int m = blockIdx.x * blockDim.x + threadIdx.x;
    if (m >= MEDGE) return;
    int t = tnode[m];
    int pos = atomicAdd(&g_cnt[t], 1);
    g_colidx[g_rowptr[t] + pos] = m;
}

// ---------------- attention alpha: 8 edges per warp, all-fp16 gathers ----------------
__global__ __launch_bounds__(256)
void alpha_kernel(const float* __restrict__ bqr,
                  const float* __restrict__ w_alpha,
                  const float* __restrict__ b_alpha,
                  const int* __restrict__ head,
                  const int* __restrict__ erel,
                  const int* __restrict__ qrel)
{
    const int m0 = (blockIdx.x * 8 + (threadIdx.x >> 5)) * 8;
    if (m0 >= MEDGE) return;
    const int lane = threadIdx.x & 31;

    int hh[8], rr[8], qq[8];
#pragma unroll
    for (int e = 0; e < 8; e++) {
        hh[e] = head[m0 + e]; rr[e] = erel[m0 + e]; qq[e] = qrel[m0 + e];
    }
    // prefetch ALL 24 gather rows (NHW + 2 rel tables, each uint4/lane)
    uint4 nv[8], rv[8], qv[8];
#pragma unroll
    for (int e = 0; e < 8; e++) {
        nv[e] = ((const uint4*)(g_NHW + (size_t)hh[e] * HDIM))[lane];
        rv[e] = ((const uint4*)(g_relWrh + rr[e] * HDIM))[lane];
        qv[e] = ((const uint4*)(g_relWqrh + qq[e] * HDIM))[lane];
    }

    const float4 bq0 = ((const float4*)bqr)[lane * 2];
    const float4 bq1 = ((const float4*)bqr)[lane * 2 + 1];
    const float4 wa0 = ((const float4*)w_alpha)[lane * 2];
    const float4 wa1 = ((const float4*)w_alpha)[lane * 2 + 1];

    float s[8];
#pragma unroll
    for (int e = 0; e < 8; e++) {
        const __half2* nh2 = (const __half2*)&nv[e];
        const __half2* rh2 = (const __half2*)&rv[e];
        const __half2* qh2 = (const __half2*)&qv[e];
        float acc = 0.f;
#pragma unroll
        for (int g = 0; g < 2; g++) {
            const float4 bq = (g == 0) ? bq0 : bq1;
            const float4 wa = (g == 0) ? wa0 : wa1;
            float2 n01 = __half22float2(nh2[g * 2]);
            float2 n23 = __half22float2(nh2[g * 2 + 1]);
            float2 r01 = __half22float2(rh2[g * 2]);
            float2 r23 = __half22float2(rh2[g * 2 + 1]);
            float2 q01 = __half22float2(qh2[g * 2]);
            float2 q23 = __half22float2(qh2[g * 2 + 1]);
            float f0 = fmaxf(n01.x + r01.x + q01.x + bq.x, 0.f);
            float f1 = fmaxf(n01.y + r01.y + q01.y + bq.y, 0.f);
            float f2 = fmaxf(n23.x + r23.x + q23.x + bq.z, 0.f);
            float f3 = fmaxf(n23.y + r23.y + q23.y + bq.w, 0.f);
            acc = fmaf(f0, wa.x, acc); acc = fmaf(f1, wa.y, acc);
            acc = fmaf(f2, wa.z, acc); acc = fmaf(f3, wa.w, acc);
        }
        s[e] = acc;
    }
#pragma unroll
    for (int o = 16; o > 0; o >>= 1) {
#pragma unroll
        for (int e = 0; e < 8; e++)
            s[e] += __shfl_xor_sync(0xffffffffu, s[e], o);
    }
    if (lane < 8) {
        float sv = s[0];
#pragma unroll
        for (int e = 1; e < 8; e++) sv = (lane == e) ? s[e] : sv;
        g_alpha[m0 + lane] = 1.f / (1.f + __expf(-(sv + b_alpha[0])));
    }
}

// ---------------- CSR aggregation: warp/node, fp16 sources ----------------
__global__ __launch_bounds__(256)
void agg_kernel(const int* __restrict__ erel,
                const int* __restrict__ tent)
{
    const int n = blockIdx.x * 8 + (threadIdx.x >> 5);
    if (n >= NNEW) return;
    const int lane = threadIdx.x & 31;
    const int s0 = g_rowptr[n], e0 = g_rowptr[n + 1];

    float4 acc0 = make_float4(0.f, 0.f, 0.f, 0.f);
    float4 acc1 = make_float4(0.f, 0.f, 0.f, 0.f);
    for (int i = s0; i < e0; i += 4) {
        const int cnt = min(4, e0 - i);
        int mm[4];
#pragma unroll
        for (int j = 0; j < 4; j++)
            if (j < cnt) mm[j] = g_colidx[i + j];
        float aa[4]; int rr[4]; uint2 tv[4];
#pragma unroll
        for (int j = 0; j < 4; j++) {
            if (j < cnt) {
                aa[j] = g_alpha[mm[j]];
                rr[j] = erel[mm[j]];
                int te = tent[mm[j]];
                tv[j] = *(const uint2*)(g_entH + (size_t)te * EDIM + lane * 4);
            }
        }
#pragma unroll
        for (int j = 0; j < 4; j++) {
            if (j < cnt) {
                const float4 hv = unpack_h(*(const uint2*)(g_relH + rr[j] * EDIM + lane * 4));
                const float4 tvf = unpack_h(tv[j]);
                const float a = aa[j];
                acc0.x = fmaf(a, hv.x, acc0.x); acc0.y = fmaf(a, hv.y, acc0.y);
                acc0.z = fmaf(a, hv.z, acc0.z); acc0.w = fmaf(a, hv.w, acc0.w);
                acc1.x = fmaf(a, tvf.x, acc1.x); acc1.y = fmaf(a, tvf.y, acc1.y);
                acc1.z = fmaf(a, tvf.z, acc1.z); acc1.w = fmaf(a, tvf.w, acc1.w);
            }
        }
    }
    __half* aggp = g_agg + (size_t)n * (2 * EDIM);
    *(uint2*)&aggp[lane * 4]        = pack_h(acc0);
    *(uint2*)&aggp[EDIM + lane * 4] = pack_h(acc1);
}

// ---------------- GRU gates + LayerNorm: warp per node ----------------
__global__ __launch_bounds__(256)
void gru_ln_kernel(const float* __restrict__ ln_g, const float* __restrict__ ln_b)
{
    const int n = blockIdx.x * 8 + (threadIdx.x >> 5);
    if (n >= NNEW) return;
    const int lane = threadIdx.x & 31;
    const __half* GX = g_GX + (size_t)n * 3 * HDIM;
    const __half* GH = g_GH + (size_t)n * 3 * HDIM;
    const int c0 = lane * 8;

    uint4 xr4 = *(const uint4*)(GX + c0);
    uint4 xz4 = *(const uint4*)(GX + HDIM + c0);
    uint4 xn4 = *(const uint4*)(GX + 2 * HDIM + c0);
    uint4 hr4 = *(const uint4*)(GH + c0);
    uint4 hz4 = *(const uint4*)(GH + HDIM + c0);
    uint4 hn4 = *(const uint4*)(GH + 2 * HDIM + c0);
    uint4 hp4 = *(const uint4*)(g_hprev + (size_t)n * HDIM + c0);

    const __half2* xr2 = (const __half2*)&xr4;
    const __half2* xz2 = (const __half2*)&xz4;
    const __half2* xn2 = (const __half2*)&xn4;
    const __half2* hr2 = (const __half2*)&hr4;
    const __half2* hz2 = (const __half2*)&hz4;
    const __half2* hn2 = (const __half2*)&hn4;
    const __half2* hp2 = (const __half2*)&hp4;

    float h[8];
    float s1 = 0.f, s2 = 0.f;
#pragma unroll
    for (int p = 0; p < 4; p++) {
        float2 xr = __half22float2(xr2[p]);
        float2 xz = __half22float2(xz2[p]);
        float2 xn = __half22float2(xn2[p]);
        float2 hr = __half22float2(hr2[p]);
        float2 hz = __half22float2(hz2[p]);
        float2 hn = __half22float2(hn2[p]);
        float2 hp = __half22float2(hp2[p]);
        float rg0 = 1.f / (1.f + __expf(-(xr.x + hr.x)));
        float rg1 = 1.f / (1.f + __expf(-(xr.y + hr.y)));
        float zg0 = 1.f / (1.f + __expf(-(xz.x + hz.x)));
        float zg1 = 1.f / (1.f + __expf(-(xz.y + hz.y)));
        float ng0 = tanhf(xn.x + rg0 * hn.x);
        float ng1 = tanhf(xn.y + rg1 * hn.y);
        h[p * 2]     = (1.f - zg0) * ng0 + zg0 * hp.x;
        h[p * 2 + 1] = (1.f - zg1) * ng1 + zg1 * hp.y;
        s1 += h[p * 2] + h[p * 2 + 1];
        s2 += h[p * 2] * h[p * 2] + h[p * 2 + 1] * h[p * 2 + 1];
    }
#pragma unroll
    for (int o = 16; o > 0; o >>= 1) {
        s1 += __shfl_xor_sync(0xffffffffu, s1, o);
        s2 += __shfl_xor_sync(0xffffffffu, s2, o);
    }
    const float mu  = s1 * (1.f / HDIM);
    const float var = s2 * (1.f / HDIM) - mu * mu;
    const float inv = rsqrtf(var + 1e-5f);

    const float4 g0 = ((const float4*)ln_g)[lane * 2];
    const float4 g1 = ((const float4*)ln_g)[lane * 2 + 1];
    const float4 b0 = ((const float4*)ln_b)[lane * 2];
    const float4 b1 = ((const float4*)ln_b)[lane * 2 + 1];

    float4 o0, o1;
    o0.x = (h[0] - mu) * inv * g0.x + b0.x;
    o0.y = (h[1] - mu) * inv * g0.y + b0.y;
    o0.z = (h[2] - mu) * inv * g0.z + b0.z;
    o0.w = (h[3] - mu) * inv * g0.w + b0.w;
    o1.x = (h[4] - mu) * inv * g1.x + b1.x;
    o1.y = (h[5] - mu) * inv * g1.y + b1.y;
    o1.z = (h[6] - mu) * inv * g1.z + b1.z;
    o1.w = (h[7] - mu) * inv * g1.w + b1.w;

    uint4 outv;
    uint2 p0 = pack_h(o0), p1 = pack_h(o1);
    outv.x = p0.x; outv.y = p0.y; outv.z = p1.x; outv.w = p1.y;
    *(uint4*)(g_hnew + (size_t)n * HDIM + c0) = outv;
}

// ---------------- final scoring: 8 edges per warp ----------------
__global__ __launch_bounds__(256)
void edge_score(const int* __restrict__ erel,
                const int* __restrict__ tent,
                const int* __restrict__ tnode,
                const int* __restrict__ bidx,
                const float* __restrict__ rankW,
                const float* __restrict__ rank_b,
                float* __restrict__ out)
{
    const int m0 = (blockIdx.x * 8 + (threadIdx.x >> 5)) * 8;
    if (m0 >= MEDGE) return;
    const int lane = threadIdx.x & 31;

    int rr[8], te[8], tt[8];
    float qd[8];
#pragma unroll
    for (int e = 0; e < 8; e++) {
        rr[e] = erel[m0 + e]; te[e] = tent[m0 + e]; tt[e] = tnode[m0 + e];
        qd[e] = g_qdot[bidx[m0 + e]];
    }
    uint4 ev[8], hv[8];
#pragma unroll
    for (int e = 0; e < 8; e++) {
        ev[e] = ((const uint4*)(g_EW1 + (size_t)te[e] * HDIM))[lane];
        hv[e] = ((const uint4*)(g_HN3 + (size_t)tt[e] * HDIM))[lane];
    }
    const float4 w0 = ((const float4*)rankW)[lane * 2];
    const float4 w1 = ((const float4*)rankW)[lane * 2 + 1];

    float s[8];
#pragma unroll
    for (int e = 0; e < 8; e++) {
        const uint4 cv = ((const uint4*)(g_relC2h + rr[e] * HDIM))[lane];
        const __half2* e2 = (const __half2*)&ev[e];
        const __half2* h2 = (const __half2*)&hv[e];
        const __half2* c2 = (const __half2*)&cv;
        float acc = 0.f;
        float2 a01 = __half22float2(e2[0]), a23 = __half22float2(e2[1]);
        float2 d01 = __half22float2(h2[0]), d23 = __half22float2(h2[1]);
        float2 c01 = __half22float2(c2[0]), c23 = __half22float2(c2[1]);
        float v0 = a01.x + c01.x + d01.x; v0 = (v0 > 0.f) ? v0 : 0.01f * v0;
        float v1 = a01.y + c01.y + d01.y; v1 = (v1 > 0.f) ? v1 : 0.01f * v1;
        float v2 = a23.x + c23.x + d23.x; v2 = (v2 > 0.f) ? v2 : 0.01f * v2;
        float v3 = a23.y + c23.y + d23.y; v3 = (v3 > 0.f) ? v3 : 0.01f * v3;
        acc = fmaf(v0, w0.x, acc); acc = fmaf(v1, w0.y, acc);
        acc = fmaf(v2, w0.z, acc); acc = fmaf(v3, w0.w, acc);
        a01 = __half22float2(e2[2]); a23 = __half22float2(e2[3]);
        d01 = __half22float2(h2[2]); d23 = __half22float2(h2[3]);
        c01 = __half22float2(c2[2]); c23 = __half22float2(c2[3]);
        v0 = a01.x + c01.x + d01.x; v0 = (v0 > 0.f) ? v0 : 0.01f * v0;
        v1 = a01.y + c01.y + d01.y; v1 = (v1 > 0.f) ? v1 : 0.01f * v1;
        v2 = a23.x + c23.x + d23.x; v2 = (v2 > 0.f) ? v2 : 0.01f * v2;
        v3 = a23.y + c23.y + d23.y; v3 = (v3 > 0.f) ? v3 : 0.01f * v3;
        acc = fmaf(v0, w1.x, acc); acc = fmaf(v1, w1.y, acc);
        acc = fmaf(v2, w1.z, acc); acc = fmaf(v3, w1.w, acc);
        s[e] = acc;
    }
#pragma unroll
    for (int o = 16; o > 0; o >>= 1) {
#pragma unroll
        for (int e = 0; e < 8; e++)
            s[e] += __shfl_xor_sync(0xffffffffu, s[e], o);
    }
    if (lane < 8) {
        float sv = s[0], qv = qd[0];
#pragma unroll
        for (int e = 1; e < 8; e++) {
            sv = (lane == e) ? s[e] : sv;
            qv = (lane == e) ? qd[e] : qv;
        }
        out[m0 + lane] = sv + qv + rank_b[0];
    }
}

// ---------------- launcher ----------------
extern "C" void kernel_launch(void* const* d_in, const int* in_sizes, int n_in,
                              void* d_out, int out_size)
{
    const float* entity_emb   = (const float*)d_in[0];
    const float* relation_emb = (const float*)d_in[1];
    const float* node_hidden  = (const float*)d_in[2];
    const float* query_repr   = (const float*)d_in[3];
    const float* Ws           = (const float*)d_in[4];
    const float* Wr           = (const float*)d_in[5];
    const float* Wqr          = (const float*)d_in[6];
    const float* bqr          = (const float*)d_in[7];
    const float* w_alpha      = (const float*)d_in[8];
    const float* b_alpha      = (const float*)d_in[9];
    const float* W_ih         = (const float*)d_in[10];
    const float* W_hh         = (const float*)d_in[11];
    const float* b_ih         = (const float*)d_in[12];
    const float* b_hh         = (const float*)d_in[13];
    const float* We2h_W       = (const float*)d_in[14];
    const float* We2h_b       = (const float*)d_in[15];
    const float* cand_W       = (const float*)d_in[16];
    const float* cand_b       = (const float*)d_in[17];
    const float* rank_W       = (const float*)d_in[18];
    const float* rank_b       = (const float*)d_in[19];
    const float* ln_g         = (const float*)d_in[20];
    const float* ln_b         = (const float*)d_in[21];
    const int* head_node      = (const int*)d_in[22];
    const int* edge_rel       = (const int*)d_in[23];
    const int* tail_ent       = (const int*)d_in[24];
    const int* tail_node      = (const int*)d_in[25];
    const int* query_rel      = (const int*)d_in[26];
    const int* batch_idx      = (const int*)d_in[27];
    const int* tail_node_ent  = (const int*)d_in[28];
    float* scores = (float*)d_out;

    __half *p_NHW, *p_EW1, *p_GX, *p_GH, *p_HN3, *p_hprev, *p_hnew, *p_agg, *p_entH;
    float *p_WsT, *p_We2hT, *p_c1T, *p_c3T;
    cudaGetSymbolAddress((void**)&p_NHW,   g_NHW);
    cudaGetSymbolAddress((void**)&p_EW1,   g_EW1);
    cudaGetSymbolAddress((void**)&p_agg,   g_agg);
    cudaGetSymbolAddress((void**)&p_hprev, g_hprev);
    cudaGetSymbolAddress((void**)&p_GX,    g_GX);
    cudaGetSymbolAddress((void**)&p_GH,    g_GH);
    cudaGetSymbolAddress((void**)&p_hnew,  g_hnew);
    cudaGetSymbolAddress((void**)&p_HN3,   g_HN3);
    cudaGetSymbolAddress((void**)&p_entH,  g_entH);
    cudaGetSymbolAddress((void**)&p_WsT,   g_WsT);
    cudaGetSymbolAddress((void**)&p_We2hT, g_We2hT);
    cudaGetSymbolAddress((void**)&p_c1T,   g_c1T);
    cudaGetSymbolAddress((void**)&p_c3T,   g_c3T);

    cudaFuncSetAttribute(hmma_gemm<0, false, true , false>, cudaFuncAttributeMaxDynamicSharedMemorySize, GEMM_DSMEM);
    cudaFuncSetAttribute(hmma_gemm<1, false, true , true >, cudaFuncAttributeMaxDynamicSharedMemorySize, GEMM_DSMEM);
    cudaFuncSetAttribute(hmma_gemm<0, false, true , true >, cudaFuncAttributeMaxDynamicSharedMemorySize, GEMM_DSMEM);
    cudaFuncSetAttribute(hmma_gemm<2, true , true , false>, cudaFuncAttributeMaxDynamicSharedMemorySize, GEMM_DSMEM);

    static cudaStream_t s1 = nullptr, s2 = nullptr;
    static cudaEvent_t evStart = nullptr, evPre = nullptr, evGH = nullptr,
                       evEW1 = nullptr, evCSR = nullptr, evRel = nullptr;
    if (s1 == nullptr) {
        cudaStreamCreateWithFlags(&s1, cudaStreamNonBlocking);
        cudaStreamCreateWithFlags(&s2, cudaStreamNonBlocking);
        cudaEventCreateWithFlags(&evStart, cudaEventDisableTiming);
        cudaEventCreateWithFlags(&evPre, cudaEventDisableTiming);
        cudaEventCreateWithFlags(&evGH, cudaEventDisableTiming);
        cudaEventCreateWithFlags(&evEW1, cudaEventDisableTiming);
        cudaEventCreateWithFlags(&evCSR, cudaEventDisableTiming);
        cudaEventCreateWithFlags(&evRel, cudaEventDisableTiming);
    }

    // ---- fork point ----
    cudaEventRecord(evStart, 0);

    // ---- s2: entity fp16 convert, then CSR build ----
    cudaStreamWaitEvent(s2, evStart, 0);
    ent_convert_kernel<<<(NENT * EDIM / 4 + 255) / 256, 256, 0, s2>>>(entity_emb);
    csr_zero_kernel<<<(NNEW + 255) / 256, 256, 0, s2>>>();
    csr_hist_kernel<<<(MEDGE + 255) / 256, 256, 0, s2>>>(tail_node);
    csr_scan1_kernel<<<NBLK, SCAN_BLK, 0, s2>>>();
    csr_scan2_kernel<<<1, SCAN_BLK, 0, s2>>>();
    csr_scan3_kernel<<<(NNEW + 255) / 256, 256, 0, s2>>>();
    csr_fill_kernel<<<(MEDGE + 255) / 256, 256, 0, s2>>>(tail_node);
    cudaEventRecord(evCSR, s2);

    // ---- s1: rel tables + qdot + rel fp16 ----
    cudaStreamWaitEvent(s1, evStart, 0);
    rel_precompute<<<NREL, 256, 0, s1>>>(relation_emb, Wr, Wqr, cand_W, cand_b);
    qdot_kernel<<<BDIM / 8, 256, 0, s1>>>(query_repr, rank_W);
    rel_convert_kernel<<<(NREL * EDIM / 4 + 255) / 256, 256, 0, s1>>>(relation_emb);
    cudaEventRecord(evRel, s1);

    // ---- main stream: weight transposes ----
    {
        TransJob j0 = {Ws, p_WsT, HDIM, HDIM};
        TransJob j1 = {We2h_W, p_We2hT, EDIM, HDIM};
        TransJob j2 = {cand_W, p_c1T, EDIM, HDIM};
        TransJob j3 = {cand_W + 2 * EDIM * HDIM, p_c3T, HDIM, HDIM};
        transpose4_kernel<<<dim3(HDIM / 32, HDIM / 32, 4), 256>>>(j0, j1, j2, j3);
    }
    cudaEventRecord(evPre, 0);

    // ---- s1 (after prep): hprev -> GH ----
    cudaStreamWaitEvent(s1, evPre, 0);
    hmma_gemm<2, true, true, false><<<dim3(2, (NNEW + 127) / 128), 256, GEMM_DSMEM, s1>>>(
        entity_emb, p_We2hT, We2h_b, p_hprev, NNEW, HDIM, EDIM, tail_node_ent);
    hmma_gemm<1, false, true, true><<<dim3(6, (NNEW + 127) / 128), 256, GEMM_DSMEM, s1>>>(
        p_hprev, W_hh, b_hh, p_GH, NNEW, 3 * HDIM, HDIM, nullptr);
    cudaEventRecord(evGH, s1);

    // ---- s2 (after convert+CSR): EW1 from fp16 entity ----
    cudaStreamWaitEvent(s2, evPre, 0);
    hmma_gemm<0, false, true, true><<<dim3(2, (NENT + 127) / 128), 256, GEMM_DSMEM, s2>>>(
        p_entH, p_c1T, nullptr, p_EW1, NENT, HDIM, EDIM, nullptr);
    cudaEventRecord(evEW1, s2);

    // ---- main: NHW -> alpha -> agg -> GX ----
    hmma_gemm<0, false, true, false><<<dim3(2, (NNODES + 127) / 128), 256, GEMM_DSMEM>>>(
        node_hidden, p_WsT, nullptr, p_NHW, NNODES, HDIM, HDIM, nullptr);
    cudaStreamWaitEvent(0, evRel, 0);
    alpha_kernel<<<(MEDGE / 8 + 7) / 8, 256>>>(
        bqr, w_alpha, b_alpha, head_node, edge_rel, query_rel);
    cudaStreamWaitEvent(0, evCSR, 0);
    agg_kernel<<<(NNEW + 7) / 8, 256>>>(edge_rel, tail_ent);
    hmma_gemm<1, false, true, true><<<dim3(6, (NNEW + 127) / 128), 256, GEMM_DSMEM>>>(
        p_agg, W_ih, b_ih, p_GX, NNEW, 3 * HDIM, 2 * EDIM, nullptr);

    // ---- join GH, GRU+LN, HN3 ----
    cudaStreamWaitEvent(0, evGH, 0);
    gru_ln_kernel<<<(NNEW + 7) / 8, 256>>>(ln_g, ln_b);
    hmma_gemm<0, false, true, true><<<dim3(2, (NNEW + 127) / 128), 256, GEMM_DSMEM>>>(
        p_hnew, p_c3T, nullptr, p_HN3, NNEW, HDIM, HDIM, nullptr);

    // ---- join EW1, final scores ----
    cudaStreamWaitEvent(0, evEW1, 0);
    edge_score<<<(MEDGE / 8 + 7) / 8, 256>>>(
        edge_rel, tail_ent, tail_node, batch_idx, rank_W, rank_b, scores);
}